// round 11
// baseline (speedup 1.0000x reference)
#include <cuda_runtime.h>
#include <cstdint>

// HashGrid2D: out[i] = table[bitmix_hash(floor(pos[i].x), floor(pos[i].y))]
// HASH_BITS=19, DIM=8, CELL_SIZE=1.0
//
// Pair-cooperative gather (2 threads per 32B row -> 1 L1 wavefront + 1 L2
// sector per row) + G=8 batching. This round: the load/store schedule is
// PINNED with asm volatile so ptxas cannot re-serialize the 8 gathers to
// save registers (R10 SASS had regs=32 == it kept only ~1 gather in flight).
// All 8 pos loads issue, then hashes, then 8 gathers back-to-back, then 8
// streaming stores.
//
// inputs: d_in[0] = positions [N,2] fp32, d_in[1] = table [2^19, 8] fp32
// output: [N, 8] fp32

#define HASH_BITS 19
#define HASH_MASK ((1u << HASH_BITS) - 1u)
#define G 8

__device__ __forceinline__ unsigned bitmix19(float px, float py)
{
    long long ix = (long long)floorf(px);   // CELL_SIZE = 1.0
    long long iy = (long long)floorf(py);
    long long h = ix;
    h ^= h >> 16;                           // arithmetic shift == jnp int64
    h *= 2246822507LL;
    h ^= h >> 13;
    h += iy * 3266489909LL;
    h ^= h >> 16;
    return (unsigned)h & HASH_MASK;         // mod 2^19, nonneg
}

// Fast path: n2 % G == 0 and grid covers T exactly (N = 2^23 here).
__global__ __launch_bounds__(256)
void hashgrid2d_pin8_kernel(const float2* __restrict__ pos,
                            const float4* __restrict__ table,  // rows = 2x float4
                            float4* __restrict__ out,
                            int T)                              // threads = n2/G
{
    int t = blockIdx.x * blockDim.x + threadIdx.x;
    int half = t & 1;   // loop-invariant: j*T is even (T = 2^21)

    // ---- phase 1: 8 pinned streaming position loads (coalesced, pair-bcast)
    float px[G], py[G];
#pragma unroll
    for (int j = 0; j < G; j++) {
        const float2* ap = &pos[(t + j * T) >> 1];
        asm volatile("ld.global.cs.v2.f32 {%0, %1}, [%2];"
                     : "=f"(px[j]), "=f"(py[j]) : "l"(ap));
    }

    // ---- phase 2: hashes (cheap ALU, overlaps outstanding pos loads' tail)
    unsigned idx[G];
#pragma unroll
    for (int j = 0; j < G; j++)
        idx[j] = bitmix19(px[j], py[j]);

    // ---- phase 3: 8 pinned gathers, all outstanding simultaneously.
    //               default .ca-equivalent caching keeps table L2-resident.
    float4 v[G];
#pragma unroll
    for (int j = 0; j < G; j++) {
        const float4* gp = table + (((size_t)idx[j] << 1) + half);
        asm volatile("ld.global.v4.f32 {%0, %1, %2, %3}, [%4];"
                     : "=f"(v[j].x), "=f"(v[j].y), "=f"(v[j].z), "=f"(v[j].w)
                     : "l"(gp));
    }

    // ---- phase 4: 8 pinned streaming stores (evict-first: protect the table)
#pragma unroll
    for (int j = 0; j < G; j++) {
        float4* op = out + (t + j * T);
        asm volatile("st.global.cs.v4.f32 [%0], {%1, %2, %3, %4};"
                     :: "l"(op), "f"(v[j].x), "f"(v[j].y), "f"(v[j].z), "f"(v[j].w)
                     : "memory");
    }
}

// Generic fallback (any N): one slot per thread, pair-cooperative.
__global__ __launch_bounds__(256)
void hashgrid2d_pair_kernel(const float2* __restrict__ pos,
                            const float4* __restrict__ table,
                            float4* __restrict__ out,
                            int n2)
{
    int t = blockIdx.x * blockDim.x + threadIdx.x;
    if (t >= n2) return;
    float2 p = pos[t >> 1];
    unsigned idx = bitmix19(p.x, p.y);
    out[t] = table[((size_t)idx << 1) + (t & 1)];
}

extern "C" void kernel_launch(void* const* d_in, const int* in_sizes, int n_in,
                              void* d_out, int out_size)
{
    const float2* pos   = (const float2*)d_in[0];
    const float4* table = (const float4*)d_in[1];
    float4*       out   = (float4*)d_out;

    int n  = in_sizes[0] / 2;   // N positions
    int n2 = n * 2;             // pair slots

    int threads = 256;
    if (n2 % (G * threads) == 0) {
        int T = n2 / G;
        hashgrid2d_pin8_kernel<<<T / threads, threads>>>(pos, table, out, T);
    } else {
        hashgrid2d_pair_kernel<<<(n2 + threads - 1) / threads, threads>>>(pos, table, out, n2);
    }
}